// round 3
// baseline (speedup 1.0000x reference)
#include <cuda_runtime.h>

// ---------------- problem constants ----------------
#define IN_DIM 256            // S*F
#define KTOT   33152          // FEAT (33152 = 259 chunks of 128)
#define KVEC   (KTOT / 4)     // float4 per W row = 8288
#define NTOT   8192           // NHEAD * S * D_MODEL
#define BATCH  8
#define S_DIM  32
#define OUT_F  64

// ---------------- gemm tiling ----------------
#define KTILE  1152                      // 9 chunks of 128 (36 KB smem)
#define NCHUNK (KTOT / 128)              // 259
#define LASTC  (NCHUNK - 1)              // 258
#define TCOLS  4                         // columns per warp
#define WARPS  8                         // warps per block
#define COLS_PER_BLOCK (WARPS * TCOLS)   // 32
#define GEMM_BLOCKS (NTOT / COLS_PER_BLOCK) // 256

// scratch (allocation-free rule: device globals)
__device__ float g_feats[BATCH * KTOT];  // [b][f]  (~1.06 MB, L2-resident)
__device__ float g_head [BATCH * NTOT];  // [b][n]  (256 KB)

using u64 = unsigned long long;

union F4U { float4 f4; u64 u[2]; float f[4]; };
union F2U { u64 u; float f[2]; };

// packed fp32x2 FMA (sm_103a)
__device__ __forceinline__ u64 ffma2(u64 a, u64 b, u64 c) {
    u64 d;
    asm("fma.rn.f32x2 %0, %1, %2, %3;" : "=l"(d) : "l"(a), "l"(b), "l"(c));
    return d;
}

// ---------------------------------------------------------------
// Kernel 1: build features
// ---------------------------------------------------------------
__global__ void feat_kernel(const float* __restrict__ x) {
    const int i = blockIdx.x;          // 0..255 (triu row)
    const int b = blockIdx.y;          // 0..7
    const int j = threadIdx.x;         // 0..255
    __shared__ float sx[IN_DIM];
    sx[j] = x[b * IN_DIM + j];
    __syncthreads();
    float* gb = g_feats + (size_t)b * KTOT;
    if (i == 0) gb[j] = sx[j];                       // linear features
    if (j >= i) {
        int off = 256 * i - (i * (i - 1)) / 2;       // triu row offset
        gb[IN_DIM + off + (j - i)] = sx[i] * sx[j];  // coalesced in j
    }
}

// ---------------------------------------------------------------
// GEMM tile body: NCH chunks, triple-buffered W pipeline (depth 2).
// Invariant entering kk: wbuf[kk%3] holds chunk g=c0+kk (ready),
// wbuf[(kk+1)%3] holds g+1 (in flight). We issue g+2 into wbuf[(kk+2)%3]
// BEFORE consuming, so its latency hides behind TWO chunks of compute.
// NCH must be ≡ 0 (mod 3) tile-start alignment: tiles of 9, tail 7,
// tail starts at chunk 252 ≡ 0 (mod 3).  (kk%3 stays compile-time.)
// ---------------------------------------------------------------
template <int NCH>
__device__ __forceinline__ void tile_body(
    int c0, const float4* __restrict__ w4,
    const unsigned rowoff[TCOLS], F4U wbuf[3][TCOLS],
    u64 acc[TCOLS][BATCH], const float* sfe, int lane)
{
#pragma unroll
    for (int kk = 0; kk < NCH; kk++) {
        // prefetch chunk g+2 (clamped; harmless re-read at the very end)
        int p = c0 + kk + 2;
        p = (p > LASTC) ? LASTC : p;
        const unsigned widx = (unsigned)p * 32u + (unsigned)lane;
#pragma unroll
        for (int t = 0; t < TCOLS; t++)
            wbuf[(kk + 2) % 3][t].f4 = __ldcs(&w4[(size_t)rowoff[t] + widx]);

        // consume chunk g from wbuf[kk%3]
        const float* fp = sfe + kk * 128 + lane * 4;
#pragma unroll
        for (int b = 0; b < BATCH; b++) {
            F4U fe; fe.f4 = *(const float4*)(fp + b * KTILE);
#pragma unroll
            for (int t = 0; t < TCOLS; t++) {
                acc[t][b] = ffma2(fe.u[0], wbuf[kk % 3][t].u[0], acc[t][b]);
                acc[t][b] = ffma2(fe.u[1], wbuf[kk % 3][t].u[1], acc[t][b]);
            }
        }
    }
}

// stage feats tile into smem: sfe[b][0..kt) = g_feats[b][k0..k0+kt)
__device__ __forceinline__ void stage_feats(float* sfe, int k0, int kt, int tid) {
    const int nv = kt >> 2;
    for (int idx = tid; idx < BATCH * nv; idx += WARPS * 32) {
        int b = idx / nv;
        int r = idx - b * nv;
        ((float4*)(sfe + b * KTILE))[r] =
            ((const float4*)(g_feats + (size_t)b * KTOT + k0))[r];
    }
}

// ---------------------------------------------------------------
// Kernel 2: head_out[b][n] = sum_f feats[b][f] * W[n][f] + bh[n]
// ---------------------------------------------------------------
__global__ void __launch_bounds__(WARPS * 32, 2)
gemm_kernel(const float* __restrict__ W, const float* __restrict__ bh) {
    __shared__ __align__(16) float sfe[BATCH * KTILE];   // 36 KB

    const int warp = threadIdx.x >> 5;
    const int lane = threadIdx.x & 31;
    const int n0 = blockIdx.x * COLS_PER_BLOCK + warp * TCOLS;

    const float4* __restrict__ w4 = (const float4*)W;
    unsigned rowoff[TCOLS];
#pragma unroll
    for (int t = 0; t < TCOLS; t++)
        rowoff[t] = (unsigned)(n0 + t) * (unsigned)KVEC;

    u64 acc[TCOLS][BATCH];
#pragma unroll
    for (int t = 0; t < TCOLS; t++)
#pragma unroll
        for (int b = 0; b < BATCH; b++) acc[t][b] = 0ull;

    // prologue: chunks 0 and 1 into wbuf[0], wbuf[1]
    F4U wbuf[3][TCOLS];
#pragma unroll
    for (int c = 0; c < 2; c++) {
        const unsigned widx = (unsigned)c * 32u + (unsigned)lane;
#pragma unroll
        for (int t = 0; t < TCOLS; t++)
            wbuf[c][t].f4 = __ldcs(&w4[(size_t)rowoff[t] + widx]);
    }

    // 28 full tiles of 9 chunks
    int c0 = 0;
    for (int k0 = 0; k0 + KTILE <= KTOT; k0 += KTILE) {
        __syncthreads();
        stage_feats(sfe, k0, KTILE, threadIdx.x);
        __syncthreads();
        tile_body<9>(c0, w4, rowoff, wbuf, acc, sfe, lane);
        c0 += 9;
    }
    // tail tile: 7 chunks (starts at chunk 252, 252 % 3 == 0)
    {
        const int k0 = 28 * KTILE;            // 32256
        __syncthreads();
        stage_feats(sfe, k0, KTOT - k0, threadIdx.x);   // 896 floats/batch
        __syncthreads();
        tile_body<7>(c0, w4, rowoff, wbuf, acc, sfe, lane);
    }

    // lane reduction + bias + store
#pragma unroll
    for (int t = 0; t < TCOLS; t++) {
        const int n = n0 + t;
        const float bias = bh[n];
#pragma unroll
        for (int b = 0; b < BATCH; b++) {
            F2U a; a.u = acc[t][b];
            float s = a.f[0] + a.f[1];
#pragma unroll
            for (int off = 16; off; off >>= 1)
                s += __shfl_xor_sync(0xffffffffu, s, off);
            if (lane == 0)
                g_head[b * NTOT + n] = s + bias;
        }
    }
}

// ---------------------------------------------------------------
// Kernel 3: output projection, one block per (b,s), 64 threads
// ---------------------------------------------------------------
__global__ void out_kernel(const float* __restrict__ Wout,
                           const float* __restrict__ bout,
                           float* __restrict__ out) {
    const int bs = blockIdx.x;          // b*32 + s
    const int b = bs >> 5, s = bs & 31;
    __shared__ __align__(16) float row[256];
    const int tid = threadIdx.x;        // of

    for (int c = tid; c < 256; c += 64) {
        int h = c >> 6, d = c & 63;
        row[c] = g_head[b * NTOT + h * (S_DIM * 64) + s * 64 + d];
    }
    __syncthreads();

    float acc = bout[tid];
    const float4* wr = (const float4*)(Wout + tid * 256);
    const float4* rr = (const float4*)row;
#pragma unroll
    for (int q = 0; q < 64; q++) {
        float4 w = wr[q];
        float4 r = rr[q];
        acc += w.x * r.x + w.y * r.y + w.z * r.z + w.w * r.w;
    }
    out[bs * 64 + tid] = acc;
}

// ---------------------------------------------------------------
extern "C" void kernel_launch(void* const* d_in, const int* in_sizes, int n_in,
                              void* d_out, int out_size) {
    const float* input   = (const float*)d_in[0];  // [8,32,8]
    const float* W_heads = (const float*)d_in[1];  // [4,2048,33152]
    const float* b_heads = (const float*)d_in[2];  // [4,2048]
    const float* W_out   = (const float*)d_in[3];  // [64,256]
    const float* b_out   = (const float*)d_in[4];  // [64]
    float* out = (float*)d_out;                    // [8,32,64]

    dim3 g1(IN_DIM, BATCH);
    feat_kernel<<<g1, IN_DIM>>>(input);
    gemm_kernel<<<GEMM_BLOCKS, WARPS * 32>>>(W_heads, b_heads);
    out_kernel<<<BATCH * S_DIM, OUT_F>>>(W_out, b_out, out);
}

// round 4
// speedup vs baseline: 2.4316x; 2.4316x over previous
#include <cuda_runtime.h>

// ---------------- problem constants ----------------
#define IN_DIM 256            // S*F
#define KTOT   33152          // FEAT = 259 chunks of 128
#define NTOT   8192           // NHEAD * S * D_MODEL
#define BATCH  8
#define S_DIM  32
#define OUT_F  64

// ---------------- gemm tiling ----------------
#define CHUNK   128                      // k per pipeline step
#define NCHUNK  (KTOT / CHUNK)           // 259
#define KTILE   512                      // feats tile = 4 chunks
#define NTILE   ((KTOT + KTILE - 1) / KTILE)  // 65 (last = 384)
#define STAGES  4                        // W smem pipeline depth
#define TCOLS   4                        // columns per warp
#define WARPS   8                        // warps per block
#define COLS_PER_BLOCK (WARPS * TCOLS)   // 32
#define GEMM_BLOCKS (NTOT / COLS_PER_BLOCK) // 256
#define W_STAGE_FLOATS (COLS_PER_BLOCK * CHUNK)       // 4096
#define SMEM_FLOATS (STAGES * W_STAGE_FLOATS + 2 * BATCH * KTILE) // 24576
#define SMEM_BYTES  (SMEM_FLOATS * 4)    // 96 KB

// scratch (allocation-free rule: device globals)
__device__ float g_feats[BATCH * KTOT];  // [b][f]  (~1.06 MB, L2-resident)
__device__ float g_head [BATCH * NTOT];  // [b][n]

using u64 = unsigned long long;
union F4U { float4 f4; u64 u[2]; float f[4]; };
union F2U { u64 u; float f[2]; };

// packed fp32x2 FMA (sm_103a)
__device__ __forceinline__ u64 ffma2(u64 a, u64 b, u64 c) {
    u64 d;
    asm("fma.rn.f32x2 %0, %1, %2, %3;" : "=l"(d) : "l"(a), "l"(b), "l"(c));
    return d;
}
// 16B async copy, L1-bypass
__device__ __forceinline__ void cpa16(float* dst, const float* src) {
    unsigned s = (unsigned)__cvta_generic_to_shared(dst);
    asm volatile("cp.async.cg.shared.global [%0], [%1], 16;" :: "r"(s), "l"(src) : "memory");
}
__device__ __forceinline__ void cpa_commit() {
    asm volatile("cp.async.commit_group;" ::: "memory");
}
__device__ __forceinline__ void cpa_wait3() {
    asm volatile("cp.async.wait_group 3;" ::: "memory");
}

// ---------------------------------------------------------------
// Kernel 1: build features
// ---------------------------------------------------------------
__global__ void feat_kernel(const float* __restrict__ x) {
    const int i = blockIdx.x, b = blockIdx.y, j = threadIdx.x;
    __shared__ float sx[IN_DIM];
    sx[j] = x[b * IN_DIM + j];
    __syncthreads();
    float* gb = g_feats + (size_t)b * KTOT;
    if (i == 0) gb[j] = sx[j];
    if (j >= i) {
        int off = 256 * i - (i * (i - 1)) / 2;
        gb[IN_DIM + off + (j - i)] = sx[i] * sx[j];
    }
}

// ---------------------------------------------------------------
// Kernel 2: head_out = feats @ W^T + bh   (HBM-bound, cp.async pipeline)
//   smem: sw[4][32][128] (W stages) | sf[2][8][512] (feats tiles)
//   group g carries W chunk g (+feats tile when g%4==3); wait_group 3
//   keeps 3 chunks in flight. Warp loads & consumes its own 4 W cols.
// ---------------------------------------------------------------
__global__ void __launch_bounds__(WARPS * 32, 2)
gemm_kernel(const float* __restrict__ W, const float* __restrict__ bh) {
    extern __shared__ __align__(16) float smem[];
    float* sw = smem;                               // [STAGES][32][128]
    float* sf = smem + STAGES * W_STAGE_FLOATS;     // [2][8][512]

    const int tid  = threadIdx.x;
    const int warp = tid >> 5;
    const int lane = tid & 31;
    const int n0   = blockIdx.x * COLS_PER_BLOCK + warp * TCOLS;

    // W issue mapping: this thread copies 4x16B of column `mycol`
    const int mycol = tid >> 3;        // 0..31
    const int myq   = tid & 7;         // 0..7
    const float* wsrc_base = W + (size_t)(blockIdx.x * COLS_PER_BLOCK + mycol) * KTOT + myq * 4;

    u64 acc[TCOLS][BATCH];
#pragma unroll
    for (int t = 0; t < TCOLS; t++)
#pragma unroll
        for (int b = 0; b < BATCH; b++) acc[t][b] = 0ull;

    // ---- prologue: groups 0..2 = W chunks 0..2 (+ feats tile 0 in G0)
#pragma unroll
    for (int c = 0; c < STAGES - 1; c++) {
        const float* src = wsrc_base + c * CHUNK;
        float* dst = sw + (c * COLS_PER_BLOCK + mycol) * CHUNK + myq * 4;
#pragma unroll
        for (int j = 0; j < 4; j++) cpa16(dst + j * 32, src + j * 32);
        if (c == 0) {   // feats tile 0 -> buffer 0
            for (int idx = tid; idx < BATCH * (KTILE / 4); idx += WARPS * 32) {
                int b = idx >> 7, r = idx & 127;   // KTILE/4 = 128
                cpa16(sf + b * KTILE + r * 4, g_feats + (size_t)b * KTOT + r * 4);
            }
        }
        cpa_commit();
    }
    asm volatile("cp.async.wait_group 2;" ::: "memory");  // G0 (feats t0) done
    __syncthreads();

    // ---- main loop over 259 chunks
    for (int kk = 0; kk < NCHUNK; kk++) {
        if ((kk & 3) == 0 && kk != 0)
            __syncthreads();   // tile swap: all warps done with old feats buf

        // issue W chunk kk+3
        const int p = kk + STAGES - 1;
        if (p < NCHUNK) {
            const float* src = wsrc_base + (size_t)p * CHUNK;
            float* dst = sw + ((p & 3) * COLS_PER_BLOCK + mycol) * CHUNK + myq * 4;
#pragma unroll
            for (int j = 0; j < 4; j++) cpa16(dst + j * 32, src + j * 32);
        }
        // issue feats tile (kk/4)+1 at tile starts
        if ((kk & 3) == 0) {
            const int Tn = (kk >> 2) + 1;
            if (Tn < NTILE) {
                const int k0 = Tn * KTILE;
                const int nv = (KTOT - k0 < KTILE ? KTOT - k0 : KTILE) >> 2; // 128 or 96
                float* fdst = sf + (Tn & 1) * BATCH * KTILE;
                for (int idx = tid; idx < BATCH * nv; idx += WARPS * 32) {
                    int b = idx / nv, r = idx - b * nv;
                    cpa16(fdst + b * KTILE + r * 4,
                          g_feats + (size_t)b * KTOT + k0 + r * 4);
                }
            }
        }
        cpa_commit();
        cpa_wait3();           // chunk kk resident
        __syncwarp();          // my warp's 4 cols fully visible

        // ---- compute chunk kk
        const float* wp = sw + ((kk & 3) * COLS_PER_BLOCK + warp * TCOLS) * CHUNK + lane * 4;
        F4U w[TCOLS];
#pragma unroll
        for (int t = 0; t < TCOLS; t++)
            w[t].f4 = *(const float4*)(wp + t * CHUNK);

        const float* fp = sf + ((kk >> 2) & 1) * BATCH * KTILE + (kk & 3) * CHUNK + lane * 4;
#pragma unroll
        for (int b = 0; b < BATCH; b++) {
            F4U fe; fe.f4 = *(const float4*)(fp + b * KTILE);
#pragma unroll
            for (int t = 0; t < TCOLS; t++) {
                acc[t][b] = ffma2(fe.u[0], w[t].u[0], acc[t][b]);
                acc[t][b] = ffma2(fe.u[1], w[t].u[1], acc[t][b]);
            }
        }
    }

    // ---- lane reduction + bias + store
#pragma unroll
    for (int t = 0; t < TCOLS; t++) {
        const int n = n0 + t;
        const float bias = bh[n];
#pragma unroll
        for (int b = 0; b < BATCH; b++) {
            F2U a; a.u = acc[t][b];
            float s = a.f[0] + a.f[1];
#pragma unroll
            for (int off = 16; off; off >>= 1)
                s += __shfl_xor_sync(0xffffffffu, s, off);
            if (lane == 0)
                g_head[b * NTOT + n] = s + bias;
        }
    }
}

// ---------------------------------------------------------------
// Kernel 3: output projection, one block per (b,s), 64 threads
// ---------------------------------------------------------------
__global__ void out_kernel(const float* __restrict__ Wout,
                           const float* __restrict__ bout,
                           float* __restrict__ out) {
    const int bs = blockIdx.x;
    const int b = bs >> 5, s = bs & 31;
    __shared__ __align__(16) float row[256];
    const int tid = threadIdx.x;

    for (int c = tid; c < 256; c += 64) {
        int h = c >> 6, d = c & 63;
        row[c] = g_head[b * NTOT + h * (S_DIM * 64) + s * 64 + d];
    }
    __syncthreads();

    float acc = bout[tid];
    const float4* wr = (const float4*)(Wout + tid * 256);
    const float4* rr = (const float4*)row;
#pragma unroll
    for (int q = 0; q < 64; q++) {
        float4 w = wr[q];
        float4 r = rr[q];
        acc += w.x * r.x + w.y * r.y + w.z * r.z + w.w * r.w;
    }
    out[bs * 64 + tid] = acc;
}

// ---------------------------------------------------------------
extern "C" void kernel_launch(void* const* d_in, const int* in_sizes, int n_in,
                              void* d_out, int out_size) {
    const float* input   = (const float*)d_in[0];  // [8,32,8]
    const float* W_heads = (const float*)d_in[1];  // [4,2048,33152]
    const float* b_heads = (const float*)d_in[2];  // [4,2048]
    const float* W_out   = (const float*)d_in[3];  // [64,256]
    const float* b_out   = (const float*)d_in[4];  // [64]
    float* out = (float*)d_out;                    // [8,32,64]

    cudaFuncSetAttribute(gemm_kernel,
                         cudaFuncAttributeMaxDynamicSharedMemorySize, SMEM_BYTES);

    dim3 g1(IN_DIM, BATCH);
    feat_kernel<<<g1, IN_DIM>>>(input);
    gemm_kernel<<<GEMM_BLOCKS, WARPS * 32, SMEM_BYTES>>>(W_heads, b_heads);
    out_kernel<<<BATCH * S_DIM, OUT_F>>>(W_out, b_out, out);
}